// round 13
// baseline (speedup 1.0000x reference)
#include <cuda_runtime.h>
#include <cuda_fp16.h>

#define NHEAD 32
#define DK    8
#define EDIM  256
#define MAXTOK (16 * 4096)

typedef unsigned long long u64;

// Scratch (static __device__: no allocation, graph-capture safe).
__device__ __half g_mid[(size_t)MAXTOK * EDIM];
__device__ __half g_Wh[EDIM * EDIM];

__device__ __forceinline__ unsigned packh2(float a, float b) {
    __half2 t = __floats2half2_rn(a, b);
    return *reinterpret_cast<unsigned*>(&t);
}

// ---- packed f32x2 helpers (sm_100a Blackwell ISA) ----
__device__ __forceinline__ u64 pk2(float lo, float hi) {
    u64 r; asm("mov.b64 %0, {%1, %2};" : "=l"(r) : "f"(lo), "f"(hi)); return r;
}
__device__ __forceinline__ void up2(u64 v, float& lo, float& hi) {
    asm("mov.b64 {%0, %1}, %2;" : "=f"(lo), "=f"(hi) : "l"(v));
}
__device__ __forceinline__ u64 fma2p(u64 a, u64 b, u64 c) {
    u64 d; asm("fma.rn.f32x2 %0, %1, %2, %3;" : "=l"(d) : "l"(a), "l"(b), "l"(c)); return d;
}
__device__ __forceinline__ u64 mul2p(u64 a, u64 b) {
    u64 d; asm("mul.rn.f32x2 %0, %1, %2;" : "=l"(d) : "l"(a), "l"(b)); return d;
}
__device__ __forceinline__ u64 add2p(u64 a, u64 b) {
    u64 d; asm("add.rn.f32x2 %0, %1, %2;" : "=l"(d) : "l"(a), "l"(b)); return d;
}
__device__ __forceinline__ float ex2f(float x) {
    float r; asm("ex2.approx.f32 %0, %1;" : "=f"(r) : "f"(x)); return r;
}

// ---------------------------------------------------------------------------
// Kernel 0: W (fp32) -> g_Wh (fp16). 65536 elems, 8 per thread.
// ---------------------------------------------------------------------------
__global__ void __launch_bounds__(256) wconv_kernel(const float* __restrict__ W)
{
    const int i = (blockIdx.x * 256 + threadIdx.x) * 8;
    float v[8];
    *reinterpret_cast<float4*>(v)     = *reinterpret_cast<const float4*>(W + i);
    *reinterpret_cast<float4*>(v + 4) = *reinterpret_cast<const float4*>(W + i + 4);
    uint4 h;
    h.x = packh2(v[0], v[1]); h.y = packh2(v[2], v[3]);
    h.z = packh2(v[4], v[5]); h.w = packh2(v[6], v[7]);
    *reinterpret_cast<uint4*>(g_Wh + i) = h;
}

// ---------------------------------------------------------------------------
// Kernel 1: quantum attention, TWO tokens per warp packed into f32x2 lanes.
// Shared tile holds float2(q_tok0, q_tok1) per (head g, dim d): one LDS.128
// and one packed FMA serve both tokens. exp via ex2 with log2e/sqrt(8) folded.
// ---------------------------------------------------------------------------
__global__ void __launch_bounds__(128) attn_kernel(
    const float* __restrict__ x,
    const float* __restrict__ theta,
    int ntok)
{
    __shared__ __align__(16) u64 qs[4][NHEAD][DK];   // 8 KB: pair-interleaved
    const int wl   = threadIdx.x >> 5;
    const int lane = threadIdx.x & 31;
    const int tok0 = (blockIdx.x * 4 + wl) * 2;
    const int tok1 = tok0 + 1;
    if (tok0 >= ntok) return;              // uniform per warp
    const bool v1 = (tok1 < ntok);

    const float4 th0 = *reinterpret_cast<const float4*>(theta);
    const float4 th1 = *reinterpret_cast<const float4*>(theta + 4);

    float q0[8], q1[8];
    {
        const float4* xp = reinterpret_cast<const float4*>(
            x + (size_t)tok0 * EDIM + lane * DK);
        const float4 a = xp[0], b = xp[1];
        q0[0] = __cosf(a.x + th0.x); q0[1] = __cosf(a.y + th0.y);
        q0[2] = __cosf(a.z + th0.z); q0[3] = __cosf(a.w + th0.w);
        q0[4] = __cosf(b.x + th1.x); q0[5] = __cosf(b.y + th1.y);
        q0[6] = __cosf(b.z + th1.z); q0[7] = __cosf(b.w + th1.w);
    }
    if (v1) {
        const float4* xp = reinterpret_cast<const float4*>(
            x + (size_t)tok1 * EDIM + lane * DK);
        const float4 a = xp[0], b = xp[1];
        q1[0] = __cosf(a.x + th0.x); q1[1] = __cosf(a.y + th0.y);
        q1[2] = __cosf(a.z + th0.z); q1[3] = __cosf(a.w + th0.w);
        q1[4] = __cosf(b.x + th1.x); q1[5] = __cosf(b.y + th1.y);
        q1[6] = __cosf(b.z + th1.z); q1[7] = __cosf(b.w + th1.w);
    } else {
#pragma unroll
        for (int i = 0; i < 8; ++i) q1[i] = 0.f;   // harmless: w=1 everywhere
    }

    u64 qp[8];
#pragma unroll
    for (int d = 0; d < 8; ++d) qp[d] = pk2(q0[d], q1[d]);

    {
        ulonglong2* row = reinterpret_cast<ulonglong2*>(&qs[wl][lane][0]);
        row[0] = make_ulonglong2(qp[0], qp[1]);
        row[1] = make_ulonglong2(qp[2], qp[3]);
        row[2] = make_ulonglong2(qp[4], qp[5]);
        row[3] = make_ulonglong2(qp[6], qp[7]);
    }
    __syncwarp();

    // exp(d/sqrt(8)) = 2^(d * log2e/sqrt(8))
    const u64 csc = pk2(0.5100420914154853f, 0.5100420914154853f);
    u64 ssp = 0ull;                       // packed (0.f, 0.f)
    u64 ac[8];
#pragma unroll
    for (int d = 0; d < 8; ++d) ac[d] = 0ull;

#pragma unroll 8
    for (int g = 0; g < NHEAD; ++g) {
        const ulonglong2* row = reinterpret_cast<const ulonglong2*>(&qs[wl][g][0]);
        const ulonglong2 r0 = row[0], r1 = row[1], r2 = row[2], r3 = row[3];
        const u64 a0 = r0.x, a1 = r0.y, a2 = r1.x, a3 = r1.y;
        const u64 a4 = r2.x, a5 = r2.y, a6 = r3.x, a7 = r3.y;

        u64 dd = mul2p(qp[0], a0);
        dd = fma2p(qp[1], a1, dd);
        dd = fma2p(qp[2], a2, dd);
        dd = fma2p(qp[3], a3, dd);
        dd = fma2p(qp[4], a4, dd);
        dd = fma2p(qp[5], a5, dd);
        dd = fma2p(qp[6], a6, dd);
        dd = fma2p(qp[7], a7, dd);
        dd = mul2p(dd, csc);

        float e0, e1;
        up2(dd, e0, e1);
        const u64 w = pk2(ex2f(e0), ex2f(e1));

        ssp = add2p(ssp, w);
        ac[0] = fma2p(w, a0, ac[0]);
        ac[1] = fma2p(w, a1, ac[1]);
        ac[2] = fma2p(w, a2, ac[2]);
        ac[3] = fma2p(w, a3, ac[3]);
        ac[4] = fma2p(w, a4, ac[4]);
        ac[5] = fma2p(w, a5, ac[5]);
        ac[6] = fma2p(w, a6, ac[6]);
        ac[7] = fma2p(w, a7, ac[7]);
    }

    float ss0, ss1;
    up2(ssp, ss0, ss1);
    float o0[8], o1[8];
#pragma unroll
    for (int d = 0; d < 8; ++d) up2(ac[d], o0[d], o1[d]);

    {
        const float inv0 = 1.0f / ss0;
        uint4 h;
        h.x = packh2(o0[0] * inv0, o0[1] * inv0);
        h.y = packh2(o0[2] * inv0, o0[3] * inv0);
        h.z = packh2(o0[4] * inv0, o0[5] * inv0);
        h.w = packh2(o0[6] * inv0, o0[7] * inv0);
        *reinterpret_cast<uint4*>(g_mid + (size_t)tok0 * EDIM + lane * DK) = h;
    }
    if (v1) {
        const float inv1 = 1.0f / ss1;
        uint4 h;
        h.x = packh2(o1[0] * inv1, o1[1] * inv1);
        h.y = packh2(o1[2] * inv1, o1[3] * inv1);
        h.z = packh2(o1[4] * inv1, o1[5] * inv1);
        h.w = packh2(o1[6] * inv1, o1[7] * inv1);
        *reinterpret_cast<uint4*>(g_mid + (size_t)tok1 * EDIM + lane * DK) = h;
    }
}

// ---------------------------------------------------------------------------
// Kernel 2: C = A @ Wh^T + bias, fp16 mma (identical to round 12).
// ---------------------------------------------------------------------------
#define GBM 128
#define GBN 128
#define GBK 32
#define KSTR 40
#define NKC  (EDIM / GBK)          // 8

__device__ __forceinline__ void mma16816h(float* d, const unsigned* a, const unsigned* b) {
    asm volatile(
        "mma.sync.aligned.m16n8k16.row.col.f32.f16.f16.f32 "
        "{%0,%1,%2,%3}, {%4,%5,%6,%7}, {%8,%9}, {%0,%1,%2,%3};\n"
        : "+f"(d[0]), "+f"(d[1]), "+f"(d[2]), "+f"(d[3])
        : "r"(a[0]), "r"(a[1]), "r"(a[2]), "r"(a[3]), "r"(b[0]), "r"(b[1]));
}

__global__ void __launch_bounds__(256) gemm_f16_kernel(
    const float* __restrict__ bias,
    float* __restrict__ C, int M)
{
    __shared__ __align__(16) __half As[GBM][KSTR];
    __shared__ __align__(16) __half Hs[GBN][KSTR];

    const int t    = threadIdx.x;
    const int warp = t >> 5;
    const int lane = t & 31;
    const int wm   = warp >> 2;      // 0..1  (M)
    const int wn   = warp & 3;       // 0..3  (N)
    const int gid  = lane >> 2;      // 0..7
    const int tig  = lane & 3;       // 0..3
    const int m0   = blockIdx.x * GBM;
    const int n0   = blockIdx.y * GBN;

    const int lr = t >> 2;           // 0..63 (rows; +64 second pass)
    const int lc = (t & 3) * 8;      // k offset (8 halves = 16B chunks)

    const __half* aB = g_mid + (size_t)m0 * EDIM;
    const __half* hB = g_Wh + (size_t)n0 * EDIM;
    const bool av0 = (m0 + lr) < M;
    const bool av1 = (m0 + lr + 64) < M;

    float acc[4][4][4];
#pragma unroll
    for (int i = 0; i < 4; ++i)
#pragma unroll
        for (int j = 0; j < 4; ++j)
#pragma unroll
            for (int c = 0; c < 4; ++c) acc[i][j][c] = 0.f;

    const uint4 zed = make_uint4(0, 0, 0, 0);
    uint4 aR0, aR1, hR0, hR1;

    aR0 = av0 ? *reinterpret_cast<const uint4*>(aB + (size_t)lr * EDIM + lc) : zed;
    aR1 = av1 ? *reinterpret_cast<const uint4*>(aB + (size_t)(lr + 64) * EDIM + lc) : zed;
    hR0 = *reinterpret_cast<const uint4*>(hB + (size_t)lr * EDIM + lc);
    hR1 = *reinterpret_cast<const uint4*>(hB + (size_t)(lr + 64) * EDIM + lc);

    for (int it = 0; it < NKC; ++it) {
        *reinterpret_cast<uint4*>(&As[lr][lc])      = aR0;
        *reinterpret_cast<uint4*>(&As[lr + 64][lc]) = aR1;
        *reinterpret_cast<uint4*>(&Hs[lr][lc])      = hR0;
        *reinterpret_cast<uint4*>(&Hs[lr + 64][lc]) = hR1;
        __syncthreads();

        if (it + 1 < NKC) {
            const int kc = (it + 1) * GBK;
            aR0 = av0 ? *reinterpret_cast<const uint4*>(aB + (size_t)lr * EDIM + kc + lc) : zed;
            aR1 = av1 ? *reinterpret_cast<const uint4*>(aB + (size_t)(lr + 64) * EDIM + kc + lc) : zed;
            hR0 = *reinterpret_cast<const uint4*>(hB + (size_t)lr * EDIM + kc + lc);
            hR1 = *reinterpret_cast<const uint4*>(hB + (size_t)(lr + 64) * EDIM + kc + lc);
        }

#pragma unroll
        for (int ks = 0; ks < 2; ++ks) {
            const int kk = ks * 16 + tig * 2;
            unsigned af[4][4], hf[4][2];
#pragma unroll
            for (int fi = 0; fi < 4; ++fi) {
                const int r = wm * 64 + fi * 16 + gid;
                af[fi][0] = *reinterpret_cast<const unsigned*>(&As[r][kk]);
                af[fi][1] = *reinterpret_cast<const unsigned*>(&As[r + 8][kk]);
                af[fi][2] = *reinterpret_cast<const unsigned*>(&As[r][kk + 8]);
                af[fi][3] = *reinterpret_cast<const unsigned*>(&As[r + 8][kk + 8]);
            }
#pragma unroll
            for (int fj = 0; fj < 4; ++fj) {
                const int r = wn * 32 + fj * 8 + gid;
                hf[fj][0] = *reinterpret_cast<const unsigned*>(&Hs[r][kk]);
                hf[fj][1] = *reinterpret_cast<const unsigned*>(&Hs[r][kk + 8]);
            }
#pragma unroll
            for (int fi = 0; fi < 4; ++fi)
#pragma unroll
                for (int fj = 0; fj < 4; ++fj)
                    mma16816h(acc[fi][fj], af[fi], hf[fj]);
        }
        __syncthreads();
    }

#pragma unroll
    for (int fj = 0; fj < 4; ++fj) {
        const int col = n0 + wn * 32 + fj * 8 + tig * 2;
        const float2 bv = *reinterpret_cast<const float2*>(&bias[col]);
#pragma unroll
        for (int fi = 0; fi < 4; ++fi) {
            const int r0 = m0 + wm * 64 + fi * 16 + gid;
            if (r0 < M)
                *reinterpret_cast<float2*>(&C[(size_t)r0 * EDIM + col]) =
                    make_float2(acc[fi][fj][0] + bv.x, acc[fi][fj][1] + bv.y);
            const int r1 = r0 + 8;
            if (r1 < M)
                *reinterpret_cast<float2*>(&C[(size_t)r1 * EDIM + col]) =
                    make_float2(acc[fi][fj][2] + bv.x, acc[fi][fj][3] + bv.y);
        }
    }
}

// ---------------------------------------------------------------------------
extern "C" void kernel_launch(void* const* d_in, const int* in_sizes, int n_in,
                              void* d_out, int out_size)
{
    const float* x     = (const float*)d_in[0];
    const float* theta = (const float*)d_in[1];
    const float* W     = (const float*)d_in[2];
    const float* bias  = (const float*)d_in[3];
    float* out = (float*)d_out;

    int ntok = in_sizes[0] / EDIM;
    if (ntok > MAXTOK) ntok = MAXTOK;

    attn_kernel<<<(ntok + 7) / 8, 128>>>(x, theta, ntok);
    wconv_kernel<<<EDIM * EDIM / (256 * 8), 256>>>(W);

    dim3 grid((ntok + GBM - 1) / GBM, EDIM / GBN);
    gemm_f16_kernel<<<grid, 256>>>(bias, out, ntok);
}

// round 14
// speedup vs baseline: 1.3902x; 1.3902x over previous
#include <cuda_runtime.h>
#include <cuda_fp16.h>

#define NHEAD 32
#define DK    8
#define EDIM  256
#define MAXTOK (16 * 4096)

// Scratch (static __device__: no allocation, graph-capture safe).
__device__ __half g_mid[(size_t)MAXTOK * EDIM];
__device__ __half g_Wh[EDIM * EDIM];

__device__ __forceinline__ unsigned packh2(float a, float b) {
    __half2 t = __floats2half2_rn(a, b);
    return *reinterpret_cast<unsigned*>(&t);
}
__device__ __forceinline__ float ex2f(float x) {
    float r; asm("ex2.approx.f32 %0, %1;" : "=f"(r) : "f"(x)); return r;
}

// ---------------------------------------------------------------------------
// Kernel 0: W (fp32) -> g_Wh (fp16). 65536 elems, 8 per thread.
// ---------------------------------------------------------------------------
__global__ void __launch_bounds__(256) wconv_kernel(const float* __restrict__ W)
{
    const int i = (blockIdx.x * 256 + threadIdx.x) * 8;
    float v[8];
    *reinterpret_cast<float4*>(v)     = *reinterpret_cast<const float4*>(W + i);
    *reinterpret_cast<float4*>(v + 4) = *reinterpret_cast<const float4*>(W + i + 4);
    uint4 h;
    h.x = packh2(v[0], v[1]); h.y = packh2(v[2], v[3]);
    h.z = packh2(v[4], v[5]); h.w = packh2(v[6], v[7]);
    *reinterpret_cast<uint4*>(g_Wh + i) = h;
}

// ---------------------------------------------------------------------------
// Kernel 1: tensor-core quantum attention. ONE warp per token.
//   S = Q Q^T   via 8x mma.m16n8k8  (A = qA rows, B = qA rows; k=8 exact)
//   W = exp(S/sqrt(8))  (bounded scores: no max pass), row sums via shfl
//   O = W Q     via 4x mma.m16n8k16 (A = w fragments in-register, B = qT)
// ---------------------------------------------------------------------------
__device__ __forceinline__ void mma_k8(float* d, unsigned a0, unsigned a1, unsigned b0) {
    asm volatile(
        "mma.sync.aligned.m16n8k8.row.col.f32.f16.f16.f32 "
        "{%0,%1,%2,%3}, {%4,%5}, {%6}, {%0,%1,%2,%3};\n"
        : "+f"(d[0]), "+f"(d[1]), "+f"(d[2]), "+f"(d[3])
        : "r"(a0), "r"(a1), "r"(b0));
}
__device__ __forceinline__ void mma_k16(float* d, const unsigned* a, const unsigned* b) {
    asm volatile(
        "mma.sync.aligned.m16n8k16.row.col.f32.f16.f16.f32 "
        "{%0,%1,%2,%3}, {%4,%5,%6,%7}, {%8,%9}, {%0,%1,%2,%3};\n"
        : "+f"(d[0]), "+f"(d[1]), "+f"(d[2]), "+f"(d[3])
        : "r"(a[0]), "r"(a[1]), "r"(a[2]), "r"(a[3]), "r"(b[0]), "r"(b[1]));
}

#define QT_STR 36   // qT row stride in halves: banks (gid*18+tig)%32 all distinct

__global__ void __launch_bounds__(128) attn_kernel(
    const float* __restrict__ x,
    const float* __restrict__ theta,
    int ntok)
{
    __shared__ __align__(16) __half qA[4][NHEAD][DK];       // 2 KB
    __shared__ __align__(16) __half qT[4][DK][QT_STR];      // 2.25 KB
    const int wl   = threadIdx.x >> 5;
    const int lane = threadIdx.x & 31;
    const int gid  = lane >> 2;      // 0..7
    const int tig  = lane & 3;       // 0..3
    const int tok  = blockIdx.x * 4 + wl;
    if (tok >= ntok) return;         // uniform per warp

    const float4 th0 = *reinterpret_cast<const float4*>(theta);
    const float4 th1 = *reinterpret_cast<const float4*>(theta + 4);

    float q[8];
    {
        const float4* xp = reinterpret_cast<const float4*>(
            x + (size_t)tok * EDIM + lane * DK);
        const float4 a = xp[0], b = xp[1];
        q[0] = __cosf(a.x + th0.x); q[1] = __cosf(a.y + th0.y);
        q[2] = __cosf(a.z + th0.z); q[3] = __cosf(a.w + th0.w);
        q[4] = __cosf(b.x + th1.x); q[5] = __cosf(b.y + th1.y);
        q[6] = __cosf(b.z + th1.z); q[7] = __cosf(b.w + th1.w);
    }

    // qA[lane][0..7] = q (fp16), one 16B store.
    {
        uint4 h;
        h.x = packh2(q[0], q[1]); h.y = packh2(q[2], q[3]);
        h.z = packh2(q[4], q[5]); h.w = packh2(q[6], q[7]);
        *reinterpret_cast<uint4*>(&qA[wl][lane][0]) = h;
    }
    // qT[d][lane] = q[d] (fp16 transpose)
#pragma unroll
    for (int d = 0; d < 8; ++d)
        qT[wl][d][lane] = __float2half_rn(q[d]);
    __syncwarp();

    // ---- Gram: S[mt*16+{gid,gid+8}][nt*8+{2tig,2tig+1}] ----
    unsigned agr[2][2], bgr[4];
#pragma unroll
    for (int mt = 0; mt < 2; ++mt) {
        agr[mt][0] = *reinterpret_cast<const unsigned*>(&qA[wl][mt * 16 + gid][2 * tig]);
        agr[mt][1] = *reinterpret_cast<const unsigned*>(&qA[wl][mt * 16 + gid + 8][2 * tig]);
    }
#pragma unroll
    for (int nt = 0; nt < 4; ++nt)
        bgr[nt] = *reinterpret_cast<const unsigned*>(&qA[wl][nt * 8 + gid][2 * tig]);

    float sc[2][4][4];
#pragma unroll
    for (int mt = 0; mt < 2; ++mt)
#pragma unroll
        for (int nt = 0; nt < 4; ++nt) {
#pragma unroll
            for (int c = 0; c < 4; ++c) sc[mt][nt][c] = 0.f;
            mma_k8(sc[mt][nt], agr[mt][0], agr[mt][1], bgr[nt]);
        }

    // ---- exp(S/sqrt(8)) = 2^(S * log2e/sqrt(8)); row sums ----
    const float CSC = 0.5100420914154853f;
    float w[2][4][4];
    float rs[2][2] = {{0.f, 0.f}, {0.f, 0.f}};
#pragma unroll
    for (int mt = 0; mt < 2; ++mt)
#pragma unroll
        for (int nt = 0; nt < 4; ++nt) {
            w[mt][nt][0] = ex2f(sc[mt][nt][0] * CSC);
            w[mt][nt][1] = ex2f(sc[mt][nt][1] * CSC);
            w[mt][nt][2] = ex2f(sc[mt][nt][2] * CSC);
            w[mt][nt][3] = ex2f(sc[mt][nt][3] * CSC);
            rs[mt][0] += w[mt][nt][0] + w[mt][nt][1];   // row mt*16+gid
            rs[mt][1] += w[mt][nt][2] + w[mt][nt][3];   // row mt*16+gid+8
        }
#pragma unroll
    for (int mt = 0; mt < 2; ++mt)
#pragma unroll
        for (int r = 0; r < 2; ++r) {
            rs[mt][r] += __shfl_xor_sync(0xFFFFFFFFu, rs[mt][r], 1);
            rs[mt][r] += __shfl_xor_sync(0xFFFFFFFFu, rs[mt][r], 2);
        }

    // ---- pack w -> fp16 A fragments (layout matches m16n8k16 A exactly) ----
    unsigned wh[2][4][2];
#pragma unroll
    for (int mt = 0; mt < 2; ++mt)
#pragma unroll
        for (int nt = 0; nt < 4; ++nt) {
            wh[mt][nt][0] = packh2(w[mt][nt][0], w[mt][nt][1]);
            wh[mt][nt][1] = packh2(w[mt][nt][2], w[mt][nt][3]);
        }

    // ---- AV: O[mt*16+rows][d] = sum_g W[row][g] q[g][d] ----
    unsigned bq[2][2];
#pragma unroll
    for (int kc = 0; kc < 2; ++kc) {
        bq[kc][0] = *reinterpret_cast<const unsigned*>(&qT[wl][gid][kc * 16 + 2 * tig]);
        bq[kc][1] = *reinterpret_cast<const unsigned*>(&qT[wl][gid][kc * 16 + 2 * tig + 8]);
    }

    float o[2][4];
#pragma unroll
    for (int mt = 0; mt < 2; ++mt) {
#pragma unroll
        for (int c = 0; c < 4; ++c) o[mt][c] = 0.f;
#pragma unroll
        for (int kc = 0; kc < 2; ++kc) {
            unsigned af[4] = { wh[mt][2 * kc][0], wh[mt][2 * kc][1],
                               wh[mt][2 * kc + 1][0], wh[mt][2 * kc + 1][1] };
            mma_k16(o[mt], af, bq[kc]);
        }
    }

    // ---- normalize + store fp16 ----
    __half* outp = g_mid + (size_t)tok * EDIM;
#pragma unroll
    for (int mt = 0; mt < 2; ++mt) {
        const float inv0 = 1.0f / rs[mt][0];
        const float inv1 = 1.0f / rs[mt][1];
        *reinterpret_cast<unsigned*>(&outp[(mt * 16 + gid) * DK + 2 * tig]) =
            packh2(o[mt][0] * inv0, o[mt][1] * inv0);
        *reinterpret_cast<unsigned*>(&outp[(mt * 16 + gid + 8) * DK + 2 * tig]) =
            packh2(o[mt][2] * inv1, o[mt][3] * inv1);
    }
}

// ---------------------------------------------------------------------------
// Kernel 2: C = A @ Wh^T + bias, fp16 mma (identical to round 12).
// ---------------------------------------------------------------------------
#define GBM 128
#define GBN 128
#define GBK 32
#define KSTR 40
#define NKC  (EDIM / GBK)          // 8

__global__ void __launch_bounds__(256) gemm_f16_kernel(
    const float* __restrict__ bias,
    float* __restrict__ C, int M)
{
    __shared__ __align__(16) __half As[GBM][KSTR];
    __shared__ __align__(16) __half Hs[GBN][KSTR];

    const int t    = threadIdx.x;
    const int warp = t >> 5;
    const int lane = t & 31;
    const int wm   = warp >> 2;      // 0..1  (M)
    const int wn   = warp & 3;       // 0..3  (N)
    const int gid  = lane >> 2;      // 0..7
    const int tig  = lane & 3;       // 0..3
    const int m0   = blockIdx.x * GBM;
    const int n0   = blockIdx.y * GBN;

    const int lr = t >> 2;           // 0..63 (rows; +64 second pass)
    const int lc = (t & 3) * 8;      // k offset (8 halves = 16B chunks)

    const __half* aB = g_mid + (size_t)m0 * EDIM;
    const __half* hB = g_Wh + (size_t)n0 * EDIM;
    const bool av0 = (m0 + lr) < M;
    const bool av1 = (m0 + lr + 64) < M;

    float acc[4][4][4];
#pragma unroll
    for (int i = 0; i < 4; ++i)
#pragma unroll
        for (int j = 0; j < 4; ++j)
#pragma unroll
            for (int c = 0; c < 4; ++c) acc[i][j][c] = 0.f;

    const uint4 zed = make_uint4(0, 0, 0, 0);
    uint4 aR0, aR1, hR0, hR1;

    aR0 = av0 ? *reinterpret_cast<const uint4*>(aB + (size_t)lr * EDIM + lc) : zed;
    aR1 = av1 ? *reinterpret_cast<const uint4*>(aB + (size_t)(lr + 64) * EDIM + lc) : zed;
    hR0 = *reinterpret_cast<const uint4*>(hB + (size_t)lr * EDIM + lc);
    hR1 = *reinterpret_cast<const uint4*>(hB + (size_t)(lr + 64) * EDIM + lc);

    for (int it = 0; it < NKC; ++it) {
        *reinterpret_cast<uint4*>(&As[lr][lc])      = aR0;
        *reinterpret_cast<uint4*>(&As[lr + 64][lc]) = aR1;
        *reinterpret_cast<uint4*>(&Hs[lr][lc])      = hR0;
        *reinterpret_cast<uint4*>(&Hs[lr + 64][lc]) = hR1;
        __syncthreads();

        if (it + 1 < NKC) {
            const int kc = (it + 1) * GBK;
            aR0 = av0 ? *reinterpret_cast<const uint4*>(aB + (size_t)lr * EDIM + kc + lc) : zed;
            aR1 = av1 ? *reinterpret_cast<const uint4*>(aB + (size_t)(lr + 64) * EDIM + kc + lc) : zed;
            hR0 = *reinterpret_cast<const uint4*>(hB + (size_t)lr * EDIM + kc + lc);
            hR1 = *reinterpret_cast<const uint4*>(hB + (size_t)(lr + 64) * EDIM + kc + lc);
        }

#pragma unroll
        for (int ks = 0; ks < 2; ++ks) {
            const int kk = ks * 16 + tig * 2;
            unsigned af[4][4], hf[4][2];
#pragma unroll
            for (int fi = 0; fi < 4; ++fi) {
                const int r = wm * 64 + fi * 16 + gid;
                af[fi][0] = *reinterpret_cast<const unsigned*>(&As[r][kk]);
                af[fi][1] = *reinterpret_cast<const unsigned*>(&As[r + 8][kk]);
                af[fi][2] = *reinterpret_cast<const unsigned*>(&As[r][kk + 8]);
                af[fi][3] = *reinterpret_cast<const unsigned*>(&As[r + 8][kk + 8]);
            }
#pragma unroll
            for (int fj = 0; fj < 4; ++fj) {
                const int r = wn * 32 + fj * 8 + gid;
                hf[fj][0] = *reinterpret_cast<const unsigned*>(&Hs[r][kk]);
                hf[fj][1] = *reinterpret_cast<const unsigned*>(&Hs[r][kk + 8]);
            }
#pragma unroll
            for (int fi = 0; fi < 4; ++fi)
#pragma unroll
                for (int fj = 0; fj < 4; ++fj)
                    mma_k16(acc[fi][fj], af[fi], hf[fj]);
        }
        __syncthreads();
    }

#pragma unroll
    for (int fj = 0; fj < 4; ++fj) {
        const int col = n0 + wn * 32 + fj * 8 + tig * 2;
        const float2 bv = *reinterpret_cast<const float2*>(&bias[col]);
#pragma unroll
        for (int fi = 0; fi < 4; ++fi) {
            const int r0 = m0 + wm * 64 + fi * 16 + gid;
            if (r0 < M)
                *reinterpret_cast<float2*>(&C[(size_t)r0 * EDIM + col]) =
                    make_float2(acc[fi][fj][0] + bv.x, acc[fi][fj][1] + bv.y);
            const int r1 = r0 + 8;
            if (r1 < M)
                *reinterpret_cast<float2*>(&C[(size_t)r1 * EDIM + col]) =
                    make_float2(acc[fi][fj][2] + bv.x, acc[fi][fj][3] + bv.y);
        }
    }
}

// ---------------------------------------------------------------------------
extern "C" void kernel_launch(void* const* d_in, const int* in_sizes, int n_in,
                              void* d_out, int out_size)
{
    const float* x     = (const float*)d_in[0];
    const float* theta = (const float*)d_in[1];
    const float* W     = (const float*)d_in[2];
    const float* bias  = (const float*)d_in[3];
    float* out = (float*)d_out;

    int ntok = in_sizes[0] / EDIM;
    if (ntok > MAXTOK) ntok = MAXTOK;

    attn_kernel<<<(ntok + 3) / 4, 128>>>(x, theta, ntok);
    wconv_kernel<<<EDIM * EDIM / (256 * 8), 256>>>(W);

    dim3 grid((ntok + GBM - 1) / GBM, EDIM / GBN);
    gemm_f16_kernel<<<grid, 256>>>(bias, out, ntok);
}